// round 17
// baseline (speedup 1.0000x reference)
#include <cuda_runtime.h>
#include <cuda_bf16.h>
#include <stdint.h>

// ============================================================================
// GumbelTopK R17: sampled window select — no histogram in the streaming passes.
//  reset:    zero histS/histA/histB/counters (1 tiny block)
//  score:    score -> exact keys32, PURE STREAM (no atomics)     [192MB]
//  samhist:  12-bit hist of first 2M keys (unbiased sample)      [8MB]
//  selectS:  pick window [lo,hi) with +-150K-element margin
//  finalcand: keys + u2 -> out; >=hi -> 1 (+exact block count);
//            in-window -> candidate staging + histA(r>>12)       [256MB]
//  selectA/histB/selectB: candidate radix, k1=k-above -> exact T, r
//  fixup2:   cand key>T -> write out; key==T -> push tie
//  tiecut:   1 block: cutoff over ties, write included ties
// m=1 gumbel: __logf fast + guard band, accurate recheck when close.
// m=0: u1 > u0 (exact, validated R12-R16).
// ============================================================================

#define N_MAX     (1u << 24)     // 4096*4096
#define HS_BINS   4096
#define HA_BINS   16384
#define HB_BINS   4096
#define SAMPLE_U4 (1 << 19)      // 512K uint4 = 2M sampled keys
#define SCALE     8u             // N / sample
#define MARGIN    150000u
#define MAX_SPAN  64u            // window width cap in 12-bit bins -> r < 2^26
#define CAND_CAP  (1u << 22)
#define TIE_CAP   65536
#define CCAP      2048
#define EPSF      1e-8f
#define EULER_F   2.7182818284590452f

__device__ unsigned int g_keys[N_MAX];
__device__ unsigned int g_cand_key[CAND_CAP];
__device__ int          g_cand_idx[CAND_CAP];
__device__ int          g_tie_idx[TIE_CAP];
__device__ unsigned int g_histS[HS_BINS];
__device__ unsigned int g_histA[HA_BINS];
__device__ unsigned int g_histB[HB_BINS];
__device__ unsigned int g_cand_cnt;
__device__ unsigned int g_tie_cnt;
__device__ unsigned int g_above_cnt;
__device__ unsigned int g_lokey;
__device__ unsigned int g_hikey;
__device__ unsigned int g_chunkA;
__device__ unsigned int g_k2;
__device__ unsigned int g_T;
__device__ unsigned int g_r;

__device__ __forceinline__ float gum(float u) {
    return -logf(-logf(u + EPSF) + EPSF);
}

__device__ __forceinline__ unsigned int f2key(float f) {
    unsigned int b = __float_as_uint(f);
    return (b & 0x80000000u) ? ~b : (b | 0x80000000u);
}

// ---------------------------------------------------------------------------
__global__ void reset_k() {
    for (int i = threadIdx.x; i < HA_BINS; i += blockDim.x) g_histA[i] = 0;
    for (int i = threadIdx.x; i < HS_BINS; i += blockDim.x) g_histS[i] = 0;
    for (int i = threadIdx.x; i < HB_BINS; i += blockDim.x) g_histB[i] = 0;
    if (threadIdx.x == 0) { g_cand_cnt = 0; g_tie_cnt = 0; g_above_cnt = 0; }
}

// ---------------------------------------------------------------------------
// score: pure streaming score -> exact key32. No smem, no atomics.
// ---------------------------------------------------------------------------
__global__ void __launch_bounds__(256) score_k(
        const float* __restrict__ logits,
        const float* __restrict__ u1,
        const int* __restrict__ training, int n4) {
    const int tr = *training;
    const int stride = gridDim.x * blockDim.x;
    for (int i = blockIdx.x * blockDim.x + threadIdx.x; i < n4; i += stride) {
        float4 l = __ldcs((const float4*)logits + i);
        float4 u = __ldcs((const float4*)u1 + i);
        uint4 kk;
        kk.x = f2key(tr ? (l.x + gum(u.x)) : l.x);
        kk.y = f2key(tr ? (l.y + gum(u.y)) : l.y);
        kk.z = f2key(tr ? (l.z + gum(u.z)) : l.z);
        kk.w = f2key(tr ? (l.w + gum(u.w)) : l.w);
        ((uint4*)g_keys)[i] = kk;
    }
}

// ---------------------------------------------------------------------------
// samhist: 12-bit histogram of the first 2M keys (unbiased sample — keys are
// iid in index order).
// ---------------------------------------------------------------------------
__global__ void __launch_bounds__(256) samhist_k() {
    __shared__ unsigned int sh[HS_BINS];     // 16 KB
    for (int i = threadIdx.x; i < HS_BINS; i += blockDim.x) sh[i] = 0;
    __syncthreads();
    const int stride = gridDim.x * blockDim.x;
    for (int i = blockIdx.x * blockDim.x + threadIdx.x; i < SAMPLE_U4; i += stride) {
        uint4 kk = ((const uint4*)g_keys)[i];
        atomicAdd(&sh[kk.x >> 20], 1u);
        atomicAdd(&sh[kk.y >> 20], 1u);
        atomicAdd(&sh[kk.z >> 20], 1u);
        atomicAdd(&sh[kk.w >> 20], 1u);
    }
    __syncthreads();
    for (int b = threadIdx.x; b < HS_BINS; b += blockDim.x) {
        unsigned int c = sh[b];
        if (c) atomicAdd(&g_histS[b], c);
    }
}

// ---------------------------------------------------------------------------
__device__ __forceinline__ unsigned int block_incl_scan(unsigned int v, unsigned int* sh) {
    int t = threadIdx.x;
    sh[t] = v;
    __syncthreads();
    for (int off = 1; off < blockDim.x; off <<= 1) {
        unsigned int add = (t >= off) ? sh[t - off] : 0u;
        __syncthreads();
        sh[t] += add;
        __syncthreads();
    }
    return sh[t];
}

// ---------------------------------------------------------------------------
// selectS: window [L, H) of 12-bit bins s.t. (with margin) the k-th element's
// bin is inside. A(b) = sampled count of bins >= b. 1 block, 1024 threads.
// ---------------------------------------------------------------------------
__global__ void selectS_k(const int* __restrict__ kp) {
    __shared__ unsigned int sh[1024];
    __shared__ unsigned int sA[HS_BINS];     // 16 KB
    __shared__ unsigned int s_H, s_L;
    const unsigned int k = (unsigned int)(*kp);
    const unsigned int thLo = (k > MARGIN) ? (k - MARGIN) : 0u;
    const unsigned int thHi = k + MARGIN;
    int t = threadIdx.x;
    if (t == 0) { s_H = HS_BINS - 1; s_L = 0; }
    unsigned int c[4], s = 0;
#pragma unroll
    for (int j = 0; j < 4; j++) { c[j] = g_histS[4095 - (4 * t + j)]; s += c[j]; }
    unsigned int incl = block_incl_scan(s, sh);
    unsigned int cum = incl - s;
#pragma unroll
    for (int j = 0; j < 4; j++) {
        cum += c[j];
        sA[4095 - (4 * t + j)] = cum;        // A(bin), inclusive
    }
    __syncthreads();
#pragma unroll
    for (int j = 0; j < 4; j++) {
        int b = 4 * t + j;
        unsigned int estb = SCALE * sA[b];
        // H = min b with est(b) <= thLo
        if (estb <= thLo && (b == 0 || SCALE * sA[b - 1] > thLo)) s_H = (unsigned int)b;
        // L = max b with est(b) >= thHi
        if (estb >= thHi && (b == HS_BINS - 1 || SCALE * sA[b + 1] < thHi)) s_L = (unsigned int)b;
    }
    __syncthreads();
    if (t == 0) {
        unsigned int H = s_H, L = s_L;
        if (H <= L) H = L + 1;
        if (H - L > MAX_SPAN) L = H - MAX_SPAN;
        g_lokey = L << 20;
        g_hikey = H << 20;
    }
}

// ---------------------------------------------------------------------------
// finalcand: keys + u2 -> out.
//  key >= hi          -> mask 1 (+ exact count)
//  key - lo < span    -> in-window: provisional 0, histA + candidate staging
//  else               -> mask 0
// m=1 gumbel: __logf + guard band, accurate logf recheck when close.
// ---------------------------------------------------------------------------
__device__ __forceinline__ float fc_elem(
        unsigned int key, int idx, float u0, float u1,
        unsigned int lo, unsigned int hi, unsigned int span, int tr,
        uint2* s_buf, int* s_cnt, int* my_above) {
    bool m = key >= hi;
    if (m) (*my_above)++;
    if (key - lo < span) {
        atomicAdd(&g_histA[(key - lo) >> 12], 1u);
        int q = atomicAdd(s_cnt, 1);
        if (q < CCAP) s_buf[q] = make_uint2(key, (unsigned int)idx);
    }
    if (!tr) return m ? 1.0f : 0.0f;
    if (m) {
        float a0 = EPSF - __logf(u0 + EPSF);
        float a1 = EPSF - __logf(u1 + EPSF);
        float lhs = EULER_F * a0;
        float d = lhs - a1;
        if (fabsf(d) > 1e-4f * (fabsf(lhs) + fabsf(a1)))
            return (d > 0.0f) ? 1.0f : 0.0f;
        float b0 = EPSF - logf(u0 + EPSF);
        float b1 = EPSF - logf(u1 + EPSF);
        return (b1 < EULER_F * b0) ? 1.0f : 0.0f;
    }
    return (u1 > u0) ? 1.0f : 0.0f;
}

__global__ void __launch_bounds__(256) finalcand_k(
        const float* __restrict__ u2,
        const int* __restrict__ training,
        float* __restrict__ out, int n4) {
    __shared__ uint2 s_buf[CCAP];    // 16 KB
    __shared__ int s_cnt;
    __shared__ unsigned int s_base;
    __shared__ int s_above[8];       // per-warp partial counts
    if (threadIdx.x == 0) s_cnt = 0;
    __syncthreads();
    const unsigned int lo = g_lokey;
    const unsigned int hi = g_hikey;
    const unsigned int span = hi - lo;
    const int tr = *training;
    const int stride = gridDim.x * blockDim.x;
    int my_above = 0;
    for (int i = blockIdx.x * blockDim.x + threadIdx.x; i < n4; i += stride) {
        uint4 kk = __ldcs((const uint4*)g_keys + i);
        float4 a = __ldcs((const float4*)u2 + 2 * i);
        float4 b = __ldcs((const float4*)u2 + 2 * i + 1);
        float4 o;
        o.x = fc_elem(kk.x, 4 * i + 0, a.x, a.y, lo, hi, span, tr, s_buf, &s_cnt, &my_above);
        o.y = fc_elem(kk.y, 4 * i + 1, a.z, a.w, lo, hi, span, tr, s_buf, &s_cnt, &my_above);
        o.z = fc_elem(kk.z, 4 * i + 2, b.x, b.y, lo, hi, span, tr, s_buf, &s_cnt, &my_above);
        o.w = fc_elem(kk.w, 4 * i + 3, b.z, b.w, lo, hi, span, tr, s_buf, &s_cnt, &my_above);
        __stcs((float4*)out + i, o);
    }
    // exact above-count: warp reduce -> block reduce -> one global atomic
    for (int off = 16; off > 0; off >>= 1)
        my_above += __shfl_down_sync(0xFFFFFFFFu, my_above, off);
    if ((threadIdx.x & 31) == 0) s_above[threadIdx.x >> 5] = my_above;
    __syncthreads();
    if (threadIdx.x == 0) {
        int tot = 0;
        for (int w = 0; w < 8; w++) tot += s_above[w];
        if (tot) atomicAdd(&g_above_cnt, (unsigned int)tot);
    }
    int cnt = s_cnt;
    if (cnt > CCAP) cnt = CCAP;
    if (threadIdx.x == 0) s_base = atomicAdd(&g_cand_cnt, (unsigned int)cnt);
    __syncthreads();
    unsigned int base = s_base;
    for (int t = threadIdx.x; t < cnt; t += blockDim.x) {
        unsigned int p = base + t;
        if (p < CAND_CAP) {
            g_cand_key[p] = s_buf[t].x;
            g_cand_idx[p] = (int)s_buf[t].y;
        }
    }
}

// ---------------------------------------------------------------------------
// selectA: 14-bit chunk of r = key - lo holding rank k1 = k - above.
// 1 block, 1024 threads x 16 bins, descending.
// ---------------------------------------------------------------------------
__global__ void selectA_k(const int* __restrict__ kp) {
    __shared__ unsigned int sh[1024];
    const unsigned int k1 = (unsigned int)(*kp) - g_above_cnt;
    int t = threadIdx.x;
    unsigned int c[16], s = 0;
#pragma unroll
    for (int j = 0; j < 16; j++) { c[j] = g_histA[HA_BINS - 1 - (16 * t + j)]; s += c[j]; }
    unsigned int incl = block_incl_scan(s, sh);
    unsigned int excl = incl - s;
    if (excl < k1 && k1 <= incl) {
        unsigned int cum = excl;
#pragma unroll
        for (int j = 0; j < 16; j++) {
            if (cum + c[j] >= k1) {
                g_chunkA = (unsigned int)(HA_BINS - 1 - (16 * t + j));
                g_k2 = k1 - cum;
                break;
            }
            cum += c[j];
        }
    }
}

// histB: candidates in selected chunk -> 12-bit histogram of r bits 11:0
__global__ void __launch_bounds__(256) histB_k() {
    const unsigned int chunk = g_chunkA;
    const unsigned int lo = g_lokey;
    unsigned int m = g_cand_cnt;
    if (m > CAND_CAP) m = CAND_CAP;
    const unsigned int stride = gridDim.x * blockDim.x;
    for (unsigned int i = blockIdx.x * blockDim.x + threadIdx.x; i < m; i += stride) {
        unsigned int r = g_cand_key[i] - lo;
        if ((r >> 12) == chunk)
            atomicAdd(&g_histB[r & 0xFFFu], 1u);
    }
}

// selectB: exact threshold T + rank r. 1 block, 1024 threads x 4 bins.
__global__ void selectB_k() {
    __shared__ unsigned int sh[1024];
    const unsigned int k2 = g_k2;
    int t = threadIdx.x;
    unsigned int c[4], s = 0;
#pragma unroll
    for (int j = 0; j < 4; j++) { c[j] = g_histB[HB_BINS - 1 - (4 * t + j)]; s += c[j]; }
    unsigned int incl = block_incl_scan(s, sh);
    unsigned int excl = incl - s;
    if (excl < k2 && k2 <= incl) {
        unsigned int cum = excl;
#pragma unroll
        for (int j = 0; j < 4; j++) {
            if (cum + c[j] >= k2) {
                unsigned int bin = (unsigned int)(HB_BINS - 1 - (4 * t + j));
                g_T = g_lokey + (g_chunkA << 12) + bin;
                g_r = k2 - cum;
                break;
            }
            cum += c[j];
        }
    }
}

// ---------------------------------------------------------------------------
// fixup2: cand key > T -> write exact m=1 result; key == T -> push tie idx.
// ---------------------------------------------------------------------------
__global__ void __launch_bounds__(256) fixup2_k(
        const float* __restrict__ u2,
        const int* __restrict__ training,
        float* __restrict__ out) {
    const unsigned int T = g_T;
    const int tr = *training;
    unsigned int m = g_cand_cnt;
    if (m > CAND_CAP) m = CAND_CAP;
    const unsigned int stride = gridDim.x * blockDim.x;
    for (unsigned int i = blockIdx.x * blockDim.x + threadIdx.x; i < m; i += stride) {
        unsigned int key = g_cand_key[i];
        if (key > T) {
            int idx = g_cand_idx[i];
            float v = 1.0f;
            if (tr) {
                float2 uu = __ldg((const float2*)u2 + idx);
                float a0 = EPSF - logf(uu.x + EPSF);
                float a1 = EPSF - logf(uu.y + EPSF);
                v = (a1 < EULER_F * a0) ? 1.0f : 0.0f;
            }
            out[idx] = v;
        } else if (key == T) {
            unsigned int p = atomicAdd(&g_tie_cnt, 1u);
            if (p < TIE_CAP) g_tie_idx[p] = g_cand_idx[i];
        }
    }
}

// ---------------------------------------------------------------------------
// tiecut: 1 block. cutoff = r-th smallest tie index; write included ties.
// ---------------------------------------------------------------------------
__global__ void tiecut_k(const float* __restrict__ u2,
                         const int* __restrict__ training,
                         float* __restrict__ out, int n) {
    __shared__ int s_cnt;
    unsigned int m = g_tie_cnt;
    if (m > TIE_CAP) m = TIE_CAP;
    const unsigned int r = g_r;
    const int tr = *training;
    if (r == 0 || m == 0) return;
    int lo = 0, hi = n - 1;
    while (lo < hi) {
        int mid = lo + (hi - lo) / 2;
        if (threadIdx.x == 0) s_cnt = 0;
        __syncthreads();
        int c = 0;
        for (unsigned int j = threadIdx.x; j < m; j += blockDim.x)
            if (g_tie_idx[j] <= mid) c++;
        if (c) atomicAdd(&s_cnt, c);
        __syncthreads();
        if (s_cnt >= (int)r) hi = mid; else lo = mid + 1;
        __syncthreads();
    }
    int cutoff = lo;
    for (unsigned int j = threadIdx.x; j < m; j += blockDim.x) {
        int idx = g_tie_idx[j];
        if (idx <= cutoff) {
            float v = 1.0f;
            if (tr) {
                float2 uu = __ldg((const float2*)u2 + idx);
                float a0 = EPSF - logf(uu.x + EPSF);
                float a1 = EPSF - logf(uu.y + EPSF);
                v = (a1 < EULER_F * a0) ? 1.0f : 0.0f;
            }
            out[idx] = v;
        }
    }
}

// ---------------------------------------------------------------------------
extern "C" void kernel_launch(void* const* d_in, const int* in_sizes, int n_in,
                              void* d_out, int out_size) {
    const float* mask_logits = (const float*)d_in[0];
    const float* u1          = (const float*)d_in[1];
    const float* u2          = (const float*)d_in[2];
    const int*   kp          = (const int*)d_in[3];
    const int*   training    = (const int*)d_in[4];
    float* out = (float*)d_out;

    const int n  = in_sizes[0];
    const int n4 = n / 4;

    reset_k<<<1, 1024>>>();
    score_k<<<4096, 256>>>(mask_logits, u1, training, n4);
    samhist_k<<<256, 256>>>();
    selectS_k<<<1, 1024>>>(kp);
    finalcand_k<<<4096, 256>>>(u2, training, out, n4);
    selectA_k<<<1, 1024>>>(kp);
    histB_k<<<512, 256>>>();
    selectB_k<<<1, 1024>>>();
    fixup2_k<<<512, 256>>>(u2, training, out);
    tiecut_k<<<1, 1024>>>(u2, training, out, n);
}